// round 4
// baseline (speedup 1.0000x reference)
#include <cuda_runtime.h>
#include <math.h>

#define NN 100000
#define EMAX 3200000
#define SCAN_BLK 1024
#define NBLK ((NN + SCAN_BLK - 1) / SCAN_BLK)   // 98

// ---------------- scratch (device globals; no allocation allowed) ------------
__device__ int   g_deg[NN];
__device__ int   g_rowptr[NN + 1];
__device__ int   g_wr[NN];
__device__ int   g_col[EMAX];
__device__ int   g_bsum[NBLK];
__device__ int   g_i64flag;
__device__ float g_agg[(size_t)NN * 64];
__device__ float g_h1 [(size_t)NN * 64];
__device__ float g_h2 [(size_t)NN * 32];

// ---------------- edge-index dtype detection + access ------------------------
// JAX default config silently downgrades int64 -> int32; detect at runtime.
__global__ void k_detect(const void* ei) {
    if (blockIdx.x == 0 && threadIdx.x == 0) {
        const long long* p = (const long long*)ei;
        int flag64 = 1;
        for (int k = 0; k < 64; k++) {
            long long v = p[k];
            if (v < 0 || v >= NN) { flag64 = 0; break; }
        }
        g_i64flag = flag64;
    }
}

__device__ __forceinline__ int edge_at(const void* ei, int E, int which, int e) {
    int v;
    if (g_i64flag) v = (int)((const long long*)ei)[(size_t)which * E + e];
    else           v = ((const int*)ei)[(size_t)which * E + e];
    // clamp: mis-read indices become wrong answers (measurable), not traps
    return min(max(v, 0), NN - 1);
}

// ---------------- CSR build --------------------------------------------------
__global__ void k_zero() {
    int i = blockIdx.x * blockDim.x + threadIdx.x;
    if (i < NN) g_deg[i] = 0;
}

__global__ void k_deg(const void* __restrict__ ei, int E) {
    int e = blockIdx.x * blockDim.x + threadIdx.x;
    if (e < E) atomicAdd(&g_deg[edge_at(ei, E, 1, e)], 1);
}

// block-local exclusive scan of g_deg into g_rowptr, block totals to g_bsum
__global__ void k_scan1() {
    __shared__ int s[SCAN_BLK];
    int i = blockIdx.x * SCAN_BLK + threadIdx.x;
    int v = (i < NN) ? g_deg[i] : 0;
    s[threadIdx.x] = v;
    __syncthreads();
    for (int off = 1; off < SCAN_BLK; off <<= 1) {
        int t = (threadIdx.x >= off) ? s[threadIdx.x - off] : 0;
        __syncthreads();
        s[threadIdx.x] += t;
        __syncthreads();
    }
    if (i < NN) g_rowptr[i] = s[threadIdx.x] - v;           // exclusive, block-local
    if (threadIdx.x == SCAN_BLK - 1) g_bsum[blockIdx.x] = s[SCAN_BLK - 1];
}

// exclusive scan of the NBLK block sums (single block)
__global__ void k_scan2() {
    __shared__ int s[128];
    int tid = threadIdx.x;
    int v = (tid < NBLK) ? g_bsum[tid] : 0;
    s[tid] = v;
    __syncthreads();
    for (int off = 1; off < 128; off <<= 1) {
        int t = (tid >= off) ? s[tid - off] : 0;
        __syncthreads();
        s[tid] += t;
        __syncthreads();
    }
    if (tid < NBLK) g_bsum[tid] = s[tid] - v;
}

__global__ void k_scan3(int E) {
    int i = blockIdx.x * SCAN_BLK + threadIdx.x;
    if (i < NN) {
        int r = g_rowptr[i] + g_bsum[blockIdx.x];
        g_rowptr[i] = r;
        g_wr[i]     = r;
    }
    if (i == 0) g_rowptr[NN] = E;
}

__global__ void k_fill(const void* __restrict__ ei, int E) {
    int e = blockIdx.x * blockDim.x + threadIdx.x;
    if (e < E) {
        int d   = edge_at(ei, E, 1, e);
        int pos = atomicAdd(&g_wr[d], 1);
        if (pos >= 0 && pos < E) g_col[pos] = edge_at(ei, E, 0, e);
    }
}

// ---------------- mean aggregation: one warp per node ------------------------
template <int D>
__device__ __forceinline__ void agg_body(const float* __restrict__ in,
                                         float* __restrict__ out) {
    int w    = (blockIdx.x * blockDim.x + threadIdx.x) >> 5;
    int lane = threadIdx.x & 31;
    if (w >= NN) return;
    int beg = g_rowptr[w], end = g_rowptr[w + 1];
    constexpr int R = D / 32;
    float acc[R];
#pragma unroll
    for (int k = 0; k < R; k++) acc[k] = 0.f;

    int base = beg;
    for (; base + 32 <= end; base += 32) {
        int j = g_col[base + lane];
#pragma unroll
        for (int t = 0; t < 32; t++) {
            int jj = __shfl_sync(0xffffffffu, j, t);
            const float* row = in + (size_t)jj * D;
#pragma unroll
            for (int k = 0; k < R; k++) acc[k] += row[lane + 32 * k];
        }
    }
    if (base < end) {
        int rem = end - base;
        int j   = (lane < rem) ? g_col[base + lane] : 0;
        for (int t = 0; t < rem; t++) {
            int jj = __shfl_sync(0xffffffffu, j, t);
            const float* row = in + (size_t)jj * D;
#pragma unroll
            for (int k = 0; k < R; k++) acc[k] += row[lane + 32 * k];
        }
    }
    float inv = 1.0f / (float)max(end - beg, 1);
#pragma unroll
    for (int k = 0; k < R; k++)
        out[(size_t)w * D + lane + 32 * k] = acc[k] * inv;
}

__global__ void k_agg1(const float* __restrict__ x) { agg_body<64>(x, g_agg); }
__global__ void k_agg2() { agg_body<64>(g_h1, g_agg); }
__global__ void k_agg3() { agg_body<32>(g_h2, g_agg); }

// ---------------- fused dual linear: out = act(agg@Wl + b + x@Wr) ------------
template <int K, int F, bool RELU>
__device__ __forceinline__ void lin_body(const float* __restrict__ aggin,
                                         const float* __restrict__ xin,
                                         const float* __restrict__ Wl,
                                         const float* __restrict__ bias,
                                         const float* __restrict__ Wr,
                                         float* __restrict__ out) {
    constexpr int NPB = 256 / F;     // nodes per block
    __shared__ float sWl[K * F];
    __shared__ float sWr[K * F];
    __shared__ float sA[NPB][K];
    __shared__ float sX[NPB][K];

    int tid = threadIdx.y * F + threadIdx.x;
    for (int idx = tid; idx < K * F; idx += 256) {
        sWl[idx] = Wl[idx];
        sWr[idx] = Wr[idx];
    }
    int node = blockIdx.x * NPB + threadIdx.y;
    if (node < NN) {
        for (int k = threadIdx.x; k < K; k += F) {
            sA[threadIdx.y][k] = aggin[(size_t)node * K + k];
            sX[threadIdx.y][k] = xin [(size_t)node * K + k];
        }
    }
    __syncthreads();
    if (node >= NN) return;

    int f = threadIdx.x;
    float acc = bias[f];
#pragma unroll
    for (int k = 0; k < K; k++)
        acc += sA[threadIdx.y][k] * sWl[k * F + f]
             + sX[threadIdx.y][k] * sWr[k * F + f];
    out[(size_t)node * F + f] = RELU ? fmaxf(acc, 0.f) : acc;
}

__global__ void k_lin1(const float* __restrict__ x,
                       const float* __restrict__ Wl, const float* __restrict__ b,
                       const float* __restrict__ Wr) {
    lin_body<64, 64, true>(g_agg, x, Wl, b, Wr, g_h1);
}
__global__ void k_lin2(const float* __restrict__ Wl, const float* __restrict__ b,
                       const float* __restrict__ Wr) {
    lin_body<64, 32, true>(g_agg, g_h1, Wl, b, Wr, g_h2);
}

// ---------------- output layer: K=32 -> 1, sigmoid ---------------------------
__global__ void k_out(const float* __restrict__ W3l, const float* __restrict__ b3,
                      const float* __restrict__ W3r, float* __restrict__ out) {
    int w    = (blockIdx.x * blockDim.x + threadIdx.x) >> 5;
    int lane = threadIdx.x & 31;
    if (w >= NN) return;
    float s = g_agg[(size_t)w * 32 + lane] * W3l[lane]
            + g_h2 [(size_t)w * 32 + lane] * W3r[lane];
#pragma unroll
    for (int off = 16; off; off >>= 1)
        s += __shfl_xor_sync(0xffffffffu, s, off);
    if (lane == 0) out[w] = 1.f / (1.f + expf(-(s + b3[0])));
}

// ---------------- launch -----------------------------------------------------
extern "C" void kernel_launch(void* const* d_in, const int* in_sizes, int n_in,
                              void* d_out, int out_size) {
    const float* x   = (const float*)d_in[0];
    const void*  ei  = d_in[1];
    const int    E   = in_sizes[1] / 2;
    const float* W1l = (const float*)d_in[2];
    const float* b1  = (const float*)d_in[3];
    const float* W1r = (const float*)d_in[4];
    const float* W2l = (const float*)d_in[5];
    const float* b2  = (const float*)d_in[6];
    const float* W2r = (const float*)d_in[7];
    const float* W3l = (const float*)d_in[8];
    const float* b3  = (const float*)d_in[9];
    const float* W3r = (const float*)d_in[10];
    float*       out = (float*)d_out;

    // CSR build (once per launch; graph-capturable, no allocation)
    k_detect<<<1, 32>>>(ei);
    k_zero <<<(NN + 255) / 256, 256>>>();
    k_deg  <<<(E + 255) / 256, 256>>>(ei, E);
    k_scan1<<<NBLK, SCAN_BLK>>>();
    k_scan2<<<1, 128>>>();
    k_scan3<<<NBLK, SCAN_BLK>>>(E);
    k_fill <<<(E + 255) / 256, 256>>>(ei, E);

    const int aggBlocks = (NN * 32 + 255) / 256;   // warp per node

    // layer 1: 64 -> 64, relu
    k_agg1<<<aggBlocks, 256>>>(x);
    k_lin1<<<(NN + 3) / 4, dim3(64, 4)>>>(x, W1l, b1, W1r);

    // layer 2: 64 -> 32, relu
    k_agg2<<<aggBlocks, 256>>>();
    k_lin2<<<(NN + 7) / 8, dim3(32, 8)>>>(W2l, b2, W2r);

    // layer 3: 32 -> 1, sigmoid
    k_agg3<<<aggBlocks, 256>>>();
    k_out <<<aggBlocks, 256>>>(W3l, b3, W3r, out);
}

// round 13
// speedup vs baseline: 1.3795x; 1.3795x over previous
#include <cuda_runtime.h>
#include <math.h>

#define NN 100000
#define EMAX 3200000
#define SCAN_BLK 1024
#define NBLK ((NN + SCAN_BLK - 1) / SCAN_BLK)   // 98
#define FULL 0xffffffffu

// ---------------- scratch (device globals; no allocation allowed) ------------
// RULE (bug in R5-R10): these may ONLY be referenced inside device code.
// Passing them as kernel arguments from kernel_launch (host) is UB.
__device__ int   g_deg[NN];
__device__ int   g_rowptr[NN + 1];
__device__ int   g_wr[NN];
__device__ int   g_col[EMAX];
__device__ int   g_bsum[NBLK];
__device__ int   g_i64flag;
__device__ __align__(16) float g_agg[(size_t)NN * 64];
__device__ __align__(16) float g_h1 [(size_t)NN * 64];
__device__ __align__(16) float g_h2 [(size_t)NN * 32];

// ---------------- edge-index dtype detection (warp-parallel) ----------------
// JAX default config silently downgrades int64 -> int32; detect at runtime.
__global__ void k_detect(const void* ei) {
    int lane = threadIdx.x;
    const long long* p = (const long long*)ei;
    long long v0 = p[lane], v1 = p[lane + 32];
    bool ok = (v0 >= 0 && v0 < NN && v1 >= 0 && v1 < NN);
    unsigned m = __ballot_sync(FULL, ok);
    if (lane == 0) g_i64flag = (m == FULL) ? 1 : 0;
}

__device__ __forceinline__ int edge_at(const void* ei, int E, int which, int e) {
    int v;
    if (g_i64flag) v = (int)((const long long*)ei)[(size_t)which * E + e];
    else           v = ((const int*)ei)[(size_t)which * E + e];
    return min(max(v, 0), NN - 1);   // clamp: wrong answers, not traps
}

// ---------------- CSR build --------------------------------------------------
__global__ void k_zero() {
    int i = blockIdx.x * blockDim.x + threadIdx.x;
    if (i < NN) g_deg[i] = 0;
}

__global__ void k_deg(const void* __restrict__ ei, int E) {
    int e = blockIdx.x * blockDim.x + threadIdx.x;
    if (e < E) atomicAdd(&g_deg[edge_at(ei, E, 1, e)], 1);   // no return -> REDG
}

__global__ void k_scan1() {
    __shared__ int s[SCAN_BLK];
    int i = blockIdx.x * SCAN_BLK + threadIdx.x;
    int v = (i < NN) ? g_deg[i] : 0;
    s[threadIdx.x] = v;
    __syncthreads();
    for (int off = 1; off < SCAN_BLK; off <<= 1) {
        int t = (threadIdx.x >= off) ? s[threadIdx.x - off] : 0;
        __syncthreads();
        s[threadIdx.x] += t;
        __syncthreads();
    }
    if (i < NN) g_rowptr[i] = s[threadIdx.x] - v;           // exclusive, block-local
    if (threadIdx.x == SCAN_BLK - 1) g_bsum[blockIdx.x] = s[SCAN_BLK - 1];
}

__global__ void k_scan2() {
    __shared__ int s[128];
    int tid = threadIdx.x;
    int v = (tid < NBLK) ? g_bsum[tid] : 0;
    s[tid] = v;
    __syncthreads();
    for (int off = 1; off < 128; off <<= 1) {
        int t = (tid >= off) ? s[tid - off] : 0;
        __syncthreads();
        s[tid] += t;
        __syncthreads();
    }
    if (tid < NBLK) g_bsum[tid] = s[tid] - v;
}

__global__ void k_scan3(int E) {
    int i = blockIdx.x * SCAN_BLK + threadIdx.x;
    if (i < NN) {
        int r = g_rowptr[i] + g_bsum[blockIdx.x];
        g_rowptr[i] = r;
        g_wr[i]     = r;
    }
    if (i == 0) g_rowptr[NN] = E;
}

__global__ void k_fill(const void* __restrict__ ei, int E) {
    int e = blockIdx.x * blockDim.x + threadIdx.x;
    if (e < E) {
        int d   = edge_at(ei, E, 1, e);
        int pos = atomicAdd(&g_wr[d], 1);
        if (pos >= 0 && pos < E) g_col[pos] = edge_at(ei, E, 0, e);
    }
}

// ---------------- mean aggregation, D=64: warp/node, float4, half-warps ------
__device__ __forceinline__ void agg64(const float* __restrict__ in,
                                      float* __restrict__ out) {
    int w    = (blockIdx.x * blockDim.x + threadIdx.x) >> 5;
    int lane = threadIdx.x & 31;
    if (w >= NN) return;
    int beg = g_rowptr[w], end = g_rowptr[w + 1];
    int h  = lane >> 4;        // half-warp id
    int li = lane & 15;        // float4 chunk within row
    float4 acc = make_float4(0.f, 0.f, 0.f, 0.f);

    int base = beg;
    for (; base + 32 <= end; base += 32) {
        int j = g_col[base + lane];
#pragma unroll
        for (int t = 0; t < 32; t += 2) {
            int jj = __shfl_sync(FULL, j, t + h);
            float4 v = ((const float4*)(in + (size_t)jj * 64))[li];
            acc.x += v.x; acc.y += v.y; acc.z += v.z; acc.w += v.w;
        }
    }
    if (base < end) {
        int rem = end - base;
        int j   = (lane < rem) ? g_col[base + lane] : 0;
        int steps = (rem + 1) >> 1;        // convergent: all lanes, all iters
        for (int s = 0; s < steps; s++) {
            int t  = 2 * s + h;
            int jj = __shfl_sync(FULL, j, (t < rem) ? t : 0);
            if (t < rem) {
                float4 v = ((const float4*)(in + (size_t)jj * 64))[li];
                acc.x += v.x; acc.y += v.y; acc.z += v.z; acc.w += v.w;
            }
        }
    }
    acc.x += __shfl_xor_sync(FULL, acc.x, 16);
    acc.y += __shfl_xor_sync(FULL, acc.y, 16);
    acc.z += __shfl_xor_sync(FULL, acc.z, 16);
    acc.w += __shfl_xor_sync(FULL, acc.w, 16);
    float inv = 1.0f / (float)max(end - beg, 1);
    if (lane < 16) {
        float4 o = make_float4(acc.x * inv, acc.y * inv, acc.z * inv, acc.w * inv);
        ((float4*)(out + (size_t)w * 64))[li] = o;
    }
}

__global__ void k_agg1(const float* __restrict__ x) { agg64(x, g_agg); }
__global__ void k_agg2() { agg64(g_h1, g_agg); }

// ---------------- fused layer 3: mean(h2)@W3l + h2@W3r + b3 -> sigmoid -------
__global__ void k_layer3(const float* __restrict__ W3l, const float* __restrict__ b3,
                         const float* __restrict__ W3r, float* __restrict__ out) {
    int w    = (blockIdx.x * blockDim.x + threadIdx.x) >> 5;
    int lane = threadIdx.x & 31;
    if (w >= NN) return;
    int beg = g_rowptr[w], end = g_rowptr[w + 1];
    int q  = lane >> 3;        // quarter-warp id (0..3)
    int li = lane & 7;         // float4 chunk within 32-wide row
    float4 acc = make_float4(0.f, 0.f, 0.f, 0.f);

    int base = beg;
    for (; base + 32 <= end; base += 32) {
        int j = g_col[base + lane];
#pragma unroll
        for (int t = 0; t < 32; t += 4) {
            int jj = __shfl_sync(FULL, j, t + q);
            float4 v = ((const float4*)(g_h2 + (size_t)jj * 32))[li];
            acc.x += v.x; acc.y += v.y; acc.z += v.z; acc.w += v.w;
        }
    }
    if (base < end) {
        int rem = end - base;
        int j   = (lane < rem) ? g_col[base + lane] : 0;
        int steps = (rem + 3) >> 2;        // convergent
        for (int s = 0; s < steps; s++) {
            int t  = 4 * s + q;
            int jj = __shfl_sync(FULL, j, (t < rem) ? t : 0);
            if (t < rem) {
                float4 v = ((const float4*)(g_h2 + (size_t)jj * 32))[li];
                acc.x += v.x; acc.y += v.y; acc.z += v.z; acc.w += v.w;
            }
        }
    }
#pragma unroll
    for (int off = 8; off <= 16; off <<= 1) {
        acc.x += __shfl_xor_sync(FULL, acc.x, off);
        acc.y += __shfl_xor_sync(FULL, acc.y, off);
        acc.z += __shfl_xor_sync(FULL, acc.z, off);
        acc.w += __shfl_xor_sync(FULL, acc.w, off);
    }
    float inv = 1.0f / (float)max(end - beg, 1);
    float s = 0.f;
    if (lane < 8) {
        float4 wl = ((const float4*)W3l)[li];
        float4 wr = ((const float4*)W3r)[li];
        float4 hv = ((const float4*)(g_h2 + (size_t)w * 32))[li];
        s = (acc.x * inv) * wl.x + (acc.y * inv) * wl.y
          + (acc.z * inv) * wl.z + (acc.w * inv) * wl.w
          + hv.x * wr.x + hv.y * wr.y + hv.z * wr.z + hv.w * wr.w;
    }
#pragma unroll
    for (int off = 4; off; off >>= 1)
        s += __shfl_xor_sync(FULL, s, off);
    if (lane == 0) out[w] = 1.f / (1.f + expf(-(s + b3[0])));
}

// ---------------- dual linear, grid-stride, weights staged once --------------
// out[node][f] = act( agg[node]@Wl + b + x[node]@Wr ), K=64 input dim.
// DEVICE impl — global buffers are bound by the __global__ wrappers below,
// never passed from host.
template <int K, int F, bool RELU>
__device__ __forceinline__ void lin_impl(const float* __restrict__ aggin,
                                         const float* __restrict__ xin,
                                         const float* __restrict__ Wl,
                                         const float* __restrict__ bias,
                                         const float* __restrict__ Wr,
                                         float* __restrict__ out) {
    constexpr int TY  = 256 / F;
    constexpr int NPB = TY * 4;            // nodes per block-iteration
    constexpr int C4  = K / 4;             // float4 chunks per row
    __shared__ float2 sW [K * F];          // (wl, wr)
    __shared__ float2 sAX[NPB][K];         // (agg, x)

    int f  = threadIdx.x;
    int ty = threadIdx.y;
    int tid = ty * F + f;

    for (int i = tid; i < K * F; i += 256)
        sW[i] = make_float2(Wl[i], Wr[i]);
    float bf = bias[f];

    for (int n0 = blockIdx.x * NPB; n0 < NN; n0 += gridDim.x * NPB) {
        for (int i = tid; i < NPB * C4; i += 256) {
            int n = i / C4, c = i % C4;
            int node = n0 + n;
            float4 va = make_float4(0.f, 0.f, 0.f, 0.f);
            float4 vx = va;
            if (node < NN) {
                va = ((const float4*)(aggin + (size_t)node * K))[c];
                vx = ((const float4*)(xin  + (size_t)node * K))[c];
            }
            sAX[n][c * 4 + 0] = make_float2(va.x, vx.x);
            sAX[n][c * 4 + 1] = make_float2(va.y, vx.y);
            sAX[n][c * 4 + 2] = make_float2(va.z, vx.z);
            sAX[n][c * 4 + 3] = make_float2(va.w, vx.w);
        }
        __syncthreads();

        float acc[4];
#pragma unroll
        for (int r = 0; r < 4; r++) acc[r] = bf;
#pragma unroll
        for (int k = 0; k < K; k++) {
            float2 wv = sW[k * F + f];
#pragma unroll
            for (int r = 0; r < 4; r++) {
                float2 ax = sAX[ty + r * TY][k];
                acc[r] = fmaf(ax.x, wv.x, acc[r]);
                acc[r] = fmaf(ax.y, wv.y, acc[r]);
            }
        }
#pragma unroll
        for (int r = 0; r < 4; r++) {
            int node = n0 + ty + r * TY;
            if (node < NN) {
                float v = acc[r];
                out[(size_t)node * F + f] = RELU ? fmaxf(v, 0.f) : v;
            }
        }
        __syncthreads();
    }
}

// wrappers: bind device globals in DEVICE code (x and weights are real args)
__global__ void k_lin1(const float* __restrict__ x,
                       const float* __restrict__ Wl, const float* __restrict__ b,
                       const float* __restrict__ Wr) {
    lin_impl<64, 64, true>(g_agg, x, Wl, b, Wr, g_h1);
}
__global__ void k_lin2(const float* __restrict__ Wl, const float* __restrict__ b,
                       const float* __restrict__ Wr) {
    lin_impl<64, 32, true>(g_agg, g_h1, Wl, b, Wr, g_h2);
}

// ---------------- launch -----------------------------------------------------
extern "C" void kernel_launch(void* const* d_in, const int* in_sizes, int n_in,
                              void* d_out, int out_size) {
    const float* x   = (const float*)d_in[0];
    const void*  ei  = d_in[1];
    const int    E   = in_sizes[1] / 2;
    const float* W1l = (const float*)d_in[2];
    const float* b1  = (const float*)d_in[3];
    const float* W1r = (const float*)d_in[4];
    const float* W2l = (const float*)d_in[5];
    const float* b2  = (const float*)d_in[6];
    const float* W2r = (const float*)d_in[7];
    const float* W3l = (const float*)d_in[8];
    const float* b3  = (const float*)d_in[9];
    const float* W3r = (const float*)d_in[10];
    float*       out = (float*)d_out;

    // CSR build (per launch; graph-capturable, no allocation)
    k_detect<<<1, 32>>>(ei);
    k_zero <<<(NN + 255) / 256, 256>>>();
    k_deg  <<<(E + 255) / 256, 256>>>(ei, E);
    k_scan1<<<NBLK, SCAN_BLK>>>();
    k_scan2<<<1, 128>>>();
    k_scan3<<<NBLK, SCAN_BLK>>>(E);
    k_fill <<<(E + 255) / 256, 256>>>(ei, E);

    const int aggBlocks = (NN * 32 + 255) / 256;   // warp per node

    // layer 1: 64 -> 64, relu
    k_agg1<<<aggBlocks, 256>>>(x);
    k_lin1<<<740, dim3(64, 4)>>>(x, W1l, b1, W1r);

    // layer 2: 64 -> 32, relu
    k_agg2<<<aggBlocks, 256>>>();
    k_lin2<<<740, dim3(32, 8)>>>(W2l, b2, W2r);

    // layer 3 (fused agg + dual linear + sigmoid): 32 -> 1
    k_layer3<<<aggBlocks, 256>>>(W3l, b3, W3r, out);
}